// round 1
// baseline (speedup 1.0000x reference)
#include <cuda_runtime.h>
#include <cuda_bf16.h>
#include <math_constants.h>

// Problem dims
#define BB 4
#define TT 2048
#define DD 1024

// Scratch (device globals — no allocation allowed)
__device__ float g_Q[(size_t)BB * TT * DD];   // 32 MB
__device__ float g_K[(size_t)BB * TT * DD];   // 32 MB
__device__ float g_V[(size_t)BB * TT * DD];   // 32 MB
__device__ float g_S[(size_t)BB * TT * TT];   // 64 MB (scores, then softmax weights in place)

// ---------------------------------------------------------------------------
// Generic fp32 SGEMM tile body: C[128x128] += A[128xK] * B
//   BT=false: B is [K,N] row-major (NN)
//   BT=true : B is [N,K] row-major, used transposed (NT, i.e. C = A * B^T)
// BM=BN=128, BK=8, TM=TN=8, 256 threads. All dims multiples of 128 / 8.
// ---------------------------------------------------------------------------
template<bool BT>
__device__ __forceinline__ void gemm_tile(
    const float* __restrict__ A, int lda,
    const float* __restrict__ Bm, int ldb,
    float* __restrict__ C, int ldc,
    int kmax, float scale)
{
    __shared__ float As[8][128];
    __shared__ float Bs[8][128];

    const int tid = threadIdx.x;
    const int tx  = tid & 15;     // 0..15 -> N direction
    const int ty  = tid >> 4;     // 0..15 -> M direction
    const int row0 = blockIdx.y * 128;
    const int col0 = blockIdx.x * 128;

    // A-tile load mapping: 128 rows x 8 k, one float4 per thread
    const int a_r = tid >> 1;
    const int a_c = (tid & 1) * 4;
    // B-tile load mapping
    const int bT_r = tid >> 1;          // BT: 128 n-rows x 8 k
    const int bT_c = (tid & 1) * 4;
    const int bN_r = tid >> 5;          // NN: 8 k-rows x 128 n
    const int bN_c = (tid & 31) * 4;

    float acc[8][8];
#pragma unroll
    for (int i = 0; i < 8; i++)
#pragma unroll
        for (int j = 0; j < 8; j++) acc[i][j] = 0.0f;

    for (int kt = 0; kt < kmax; kt += 8) {
        // Stage A (transposed into As[k][m])
        float4 av = *(const float4*)(A + (size_t)(row0 + a_r) * lda + kt + a_c);
        As[a_c + 0][a_r] = av.x;
        As[a_c + 1][a_r] = av.y;
        As[a_c + 2][a_r] = av.z;
        As[a_c + 3][a_r] = av.w;

        if (BT) {
            float4 bv = *(const float4*)(Bm + (size_t)(col0 + bT_r) * ldb + kt + bT_c);
            Bs[bT_c + 0][bT_r] = bv.x;
            Bs[bT_c + 1][bT_r] = bv.y;
            Bs[bT_c + 2][bT_r] = bv.z;
            Bs[bT_c + 3][bT_r] = bv.w;
        } else {
            float4 bv = *(const float4*)(Bm + (size_t)(kt + bN_r) * ldb + col0 + bN_c);
            *(float4*)&Bs[bN_r][bN_c] = bv;
        }
        __syncthreads();

#pragma unroll
        for (int k = 0; k < 8; k++) {
            float a[8], b[8];
            *(float4*)&a[0] = *(const float4*)&As[k][ty * 8];
            *(float4*)&a[4] = *(const float4*)&As[k][ty * 8 + 4];
            *(float4*)&b[0] = *(const float4*)&Bs[k][tx * 8];
            *(float4*)&b[4] = *(const float4*)&Bs[k][tx * 8 + 4];
#pragma unroll
            for (int i = 0; i < 8; i++)
#pragma unroll
                for (int j = 0; j < 8; j++)
                    acc[i][j] += a[i] * b[j];
        }
        __syncthreads();
    }

#pragma unroll
    for (int i = 0; i < 8; i++) {
#pragma unroll
        for (int j = 0; j < 8; j += 4) {
            float4 v;
            v.x = acc[i][j + 0] * scale;
            v.y = acc[i][j + 1] * scale;
            v.z = acc[i][j + 2] * scale;
            v.w = acc[i][j + 3] * scale;
            *(float4*)(C + (size_t)(row0 + ty * 8 + i) * ldc + col0 + tx * 8 + j) = v;
        }
    }
}

// ---------------------------------------------------------------------------
// Kernel 1: QKV projections. grid = (DD/128, B*T/128, 3)
// ---------------------------------------------------------------------------
__global__ void __launch_bounds__(256, 2) k_proj(
    const float* __restrict__ X,
    const float* __restrict__ Wq,
    const float* __restrict__ Wk,
    const float* __restrict__ Wv)
{
    const float* W;
    float* C;
    if (blockIdx.z == 0)      { W = Wq; C = g_Q; }
    else if (blockIdx.z == 1) { W = Wk; C = g_K; }
    else                      { W = Wv; C = g_V; }
    gemm_tile<false>(X, DD, W, DD, C, DD, DD, 1.0f);
}

// ---------------------------------------------------------------------------
// Kernel 2: S_b = (Q_b K_b^T) / 32, lower-triangular blocks only.
// grid = (T/128, T/128, B)
// ---------------------------------------------------------------------------
__global__ void __launch_bounds__(256, 2) k_scores()
{
    if (blockIdx.x > blockIdx.y) return;  // block fully above diagonal
    const int b = blockIdx.z;
    gemm_tile<true>(g_Q + (size_t)b * TT * DD, DD,
                    g_K + (size_t)b * TT * DD, DD,
                    g_S + (size_t)b * TT * TT, TT,
                    DD, 0.03125f);
}

// ---------------------------------------------------------------------------
// Kernel 3: causal row softmax in place on g_S. grid = B*T blocks, 256 thr.
// Writes 0 for masked (j > i) positions.
// ---------------------------------------------------------------------------
__global__ void __launch_bounds__(256) k_softmax()
{
    const int row = blockIdx.x;          // 0 .. B*T-1
    const int i   = row & (TT - 1);
    float* s = g_S + (size_t)row * TT;
    const int L = i + 1;
    const int tid = threadIdx.x;
    __shared__ float red[256];

    float m = -CUDART_INF_F;
    for (int j = tid; j < L; j += 256) m = fmaxf(m, s[j]);
    red[tid] = m;
    __syncthreads();
    for (int w = 128; w > 0; w >>= 1) {
        if (tid < w) red[tid] = fmaxf(red[tid], red[tid + w]);
        __syncthreads();
    }
    m = red[0];
    __syncthreads();

    float sum = 0.0f;
    for (int j = tid; j < L; j += 256) sum += __expf(s[j] - m);
    red[tid] = sum;
    __syncthreads();
    for (int w = 128; w > 0; w >>= 1) {
        if (tid < w) red[tid] += red[tid + w];
        __syncthreads();
    }
    const float inv = 1.0f / red[0];

    for (int j = tid; j < TT; j += 256) {
        float v = (j < L) ? __expf(s[j] - m) * inv : 0.0f;
        s[j] = v;
    }
}

// ---------------------------------------------------------------------------
// Kernel 4: O_b = W_b V_b, k-range clamped to causal extent.
// grid = (DD/128, T/128, B)
// ---------------------------------------------------------------------------
__global__ void __launch_bounds__(256, 2) k_pv(float* __restrict__ out)
{
    const int b = blockIdx.z;
    const int kmax = (blockIdx.y + 1) * 128;   // weights are 0 beyond row index
    gemm_tile<false>(g_S + (size_t)b * TT * TT, TT,
                     g_V + (size_t)b * TT * DD, DD,
                     out + (size_t)b * TT * DD, DD,
                     kmax, 1.0f);
}

// ---------------------------------------------------------------------------
extern "C" void kernel_launch(void* const* d_in, const int* in_sizes, int n_in,
                              void* d_out, int out_size)
{
    const float* X  = (const float*)d_in[0];
    const float* Wq = (const float*)d_in[1];
    const float* Wk = (const float*)d_in[2];
    const float* Wv = (const float*)d_in[3];
    float* out = (float*)d_out;

    k_proj   <<<dim3(DD / 128, (BB * TT) / 128, 3), 256>>>(X, Wq, Wk, Wv);
    k_scores <<<dim3(TT / 128, TT / 128, BB), 256>>>();
    k_softmax<<<BB * TT, 256>>>();
    k_pv     <<<dim3(DD / 128, TT / 128, BB), 256>>>(out);
}

// round 3
// speedup vs baseline: 1.1197x; 1.1197x over previous
#include <cuda_runtime.h>
#include <cuda_bf16.h>
#include <math_constants.h>

// Problem dims
#define BB 4
#define TT 2048
#define DD 1024

typedef unsigned long long u64;

// Scratch (device globals — no allocation allowed)
__device__ float g_Q[(size_t)BB * TT * DD];   // 32 MB
__device__ float g_K[(size_t)BB * TT * DD];   // 32 MB
__device__ float g_V[(size_t)BB * TT * DD];   // 32 MB
__device__ float g_S[(size_t)BB * TT * TT];   // 64 MB

// ---- packed f32x2 helpers (sm_100+) ------------------------------------
__device__ __forceinline__ u64 dup2(float x) {
    u64 r; asm("mov.b64 %0, {%1, %1};" : "=l"(r) : "f"(x)); return r;
}
__device__ __forceinline__ void ffma2(u64& c, u64 a, u64 b) {
    asm("fma.rn.f32x2 %0, %1, %2, %0;" : "+l"(c) : "l"(a), "l"(b));
}
__device__ __forceinline__ float2 unpack2(u64 v) {
    float2 f; asm("mov.b64 {%0, %1}, %2;" : "=f"(f.x), "=f"(f.y) : "l"(v)); return f;
}

// ---------------------------------------------------------------------------
// fp32 SGEMM tile: C[128x128] = scale * A[128xK] * op(B)
//   BT=false: B is [K,N] row-major (NN)
//   BT=true : B is [N,K] row-major, used transposed (NT)
// BM=BN=128, BK=16, double-buffered smem, packed f32x2 FMA inner loop.
// 256 threads; each computes an 8x8 microtile as 8x4 f32x2 accumulators.
// ---------------------------------------------------------------------------
template<bool BT>
__device__ __forceinline__ void gemm_tile(
    const float* __restrict__ A, int lda,
    const float* __restrict__ Bm, int ldb,
    float* __restrict__ C, int ldc,
    int kmax, float scale)
{
    __shared__ float As[2][16][128];
    __shared__ float Bs[2][16][128];

    const int tid = threadIdx.x;
    const int tx  = tid & 15;     // N direction
    const int ty  = tid >> 4;     // M direction
    const int row0 = blockIdx.y * 128;
    const int col0 = blockIdx.x * 128;

    // staging maps: 128 rows x 16 k (A and NT-B): row=tid>>1, 8 k per thread
    const int ar = tid >> 1;
    const int ac = (tid & 1) * 8;
    // NN-B: 16 k-rows x 128 n
    const int bkr = tid >> 4;
    const int bnc = (tid & 15) * 8;

    const float* Aptr = A + (size_t)(row0 + ar) * lda + ac;
    const float* Bptr = BT ? (Bm + (size_t)(col0 + ar) * ldb + ac)
                           : (Bm + (size_t)bkr * ldb + col0 + bnc);

    u64 acc[8][4];
#pragma unroll
    for (int i = 0; i < 8; i++)
#pragma unroll
        for (int j = 0; j < 4; j++) acc[i][j] = 0ull;

    // ---- prologue: stage tile 0 into buffer 0 ----
    {
        float4 a0 = *(const float4*)(Aptr);
        float4 a1 = *(const float4*)(Aptr + 4);
#pragma unroll
        for (int i = 0; i < 4; i++) {
            As[0][ac + i][ar]     = ((const float*)&a0)[i];
            As[0][ac + 4 + i][ar] = ((const float*)&a1)[i];
        }
        float4 b0 = *(const float4*)(Bptr);
        float4 b1 = *(const float4*)(Bptr + 4);
        if (BT) {
#pragma unroll
            for (int i = 0; i < 4; i++) {
                Bs[0][ac + i][ar]     = ((const float*)&b0)[i];
                Bs[0][ac + 4 + i][ar] = ((const float*)&b1)[i];
            }
        } else {
            *(float4*)&Bs[0][bkr][bnc]     = b0;
            *(float4*)&Bs[0][bkr][bnc + 4] = b1;
        }
    }
    __syncthreads();

    const int nk = kmax >> 4;
    for (int t = 0; t < nk; t++) {
        const int buf = t & 1;

        // prefetch next tile into registers (overlaps with compute)
        float4 pa0, pa1, pb0, pb1;
        const bool has_next = (t + 1 < nk);
        if (has_next) {
            const float* Ap = Aptr + (t + 1) * 16;
            pa0 = *(const float4*)Ap;
            pa1 = *(const float4*)(Ap + 4);
            const float* Bp = BT ? (Bptr + (t + 1) * 16)
                                 : (Bptr + (size_t)(t + 1) * 16 * ldb);
            pb0 = *(const float4*)Bp;
            pb1 = *(const float4*)(Bp + 4);
        }

        // compute 16 k-steps from smem[buf]
#pragma unroll
        for (int k = 0; k < 16; k++) {
            float4 alo = *(const float4*)&As[buf][k][ty * 8];
            float4 ahi = *(const float4*)&As[buf][k][ty * 8 + 4];
            ulonglong2 bA = *(const ulonglong2*)&Bs[buf][k][tx * 8];
            ulonglong2 bB = *(const ulonglong2*)&Bs[buf][k][tx * 8 + 4];
            u64 b2[4] = { bA.x, bA.y, bB.x, bB.y };
            float a8[8] = { alo.x, alo.y, alo.z, alo.w,
                            ahi.x, ahi.y, ahi.z, ahi.w };
#pragma unroll
            for (int i = 0; i < 8; i++) {
                u64 ad = dup2(a8[i]);
#pragma unroll
                for (int j = 0; j < 4; j++) ffma2(acc[i][j], ad, b2[j]);
            }
        }

        // drain staged regs into the other buffer
        if (has_next) {
            const int nb = buf ^ 1;
#pragma unroll
            for (int i = 0; i < 4; i++) {
                As[nb][ac + i][ar]     = ((const float*)&pa0)[i];
                As[nb][ac + 4 + i][ar] = ((const float*)&pa1)[i];
            }
            if (BT) {
#pragma unroll
                for (int i = 0; i < 4; i++) {
                    Bs[nb][ac + i][ar]     = ((const float*)&pb0)[i];
                    Bs[nb][ac + 4 + i][ar] = ((const float*)&pb1)[i];
                }
            } else {
                *(float4*)&Bs[nb][bkr][bnc]     = pb0;
                *(float4*)&Bs[nb][bkr][bnc + 4] = pb1;
            }
        }
        __syncthreads();
    }

    // ---- epilogue ----
#pragma unroll
    for (int i = 0; i < 8; i++) {
        float2 p0 = unpack2(acc[i][0]);
        float2 p1 = unpack2(acc[i][1]);
        float2 p2 = unpack2(acc[i][2]);
        float2 p3 = unpack2(acc[i][3]);
        float* Crow = C + (size_t)(row0 + ty * 8 + i) * ldc + col0 + tx * 8;
        float4 o0 = make_float4(p0.x * scale, p0.y * scale, p1.x * scale, p1.y * scale);
        float4 o1 = make_float4(p2.x * scale, p2.y * scale, p3.x * scale, p3.y * scale);
        *(float4*)(Crow)     = o0;
        *(float4*)(Crow + 4) = o1;
    }
}

// ---------------------------------------------------------------------------
// Kernel 1: QKV projections. grid = (DD/128, B*T/128, 3)
// ---------------------------------------------------------------------------
__global__ void __launch_bounds__(256, 2) k_proj(
    const float* __restrict__ X,
    const float* __restrict__ Wq,
    const float* __restrict__ Wk,
    const float* __restrict__ Wv)
{
    const float* W;
    float* C;
    if (blockIdx.z == 0)      { W = Wq; C = g_Q; }
    else if (blockIdx.z == 1) { W = Wk; C = g_K; }
    else                      { W = Wv; C = g_V; }
    gemm_tile<false>(X, DD, W, DD, C, DD, DD, 1.0f);
}

// ---------------------------------------------------------------------------
// Kernel 2: S_b = (Q_b K_b^T) / 32, lower-triangular blocks only.
// ---------------------------------------------------------------------------
__global__ void __launch_bounds__(256, 2) k_scores()
{
    if (blockIdx.x > blockIdx.y) return;
    const int b = blockIdx.z;
    gemm_tile<true>(g_Q + (size_t)b * TT * DD, DD,
                    g_K + (size_t)b * TT * DD, DD,
                    g_S + (size_t)b * TT * TT, TT,
                    DD, 0.03125f);
}

// ---------------------------------------------------------------------------
// Kernel 3: causal row softmax in place on g_S. grid = B*T blocks, 256 thr.
// ---------------------------------------------------------------------------
__global__ void __launch_bounds__(256) k_softmax()
{
    const int row = blockIdx.x;
    const int i   = row & (TT - 1);
    float* s = g_S + (size_t)row * TT;
    const int L = i + 1;
    const int tid = threadIdx.x;
    __shared__ float red[256];

    float m = -CUDART_INF_F;
    for (int j = tid; j < L; j += 256) m = fmaxf(m, s[j]);
    red[tid] = m;
    __syncthreads();
    for (int w = 128; w > 0; w >>= 1) {
        if (tid < w) red[tid] = fmaxf(red[tid], red[tid + w]);
        __syncthreads();
    }
    m = red[0];
    __syncthreads();

    float sum = 0.0f;
    for (int j = tid; j < L; j += 256) sum += __expf(s[j] - m);
    red[tid] = sum;
    __syncthreads();
    for (int w = 128; w > 0; w >>= 1) {
        if (tid < w) red[tid] += red[tid + w];
        __syncthreads();
    }
    const float inv = 1.0f / red[0];

    for (int j = tid; j < TT; j += 256) {
        float v = (j < L) ? __expf(s[j] - m) * inv : 0.0f;
        s[j] = v;
    }
}

// ---------------------------------------------------------------------------
// Kernel 4: O_b = W_b V_b, k-range clamped to causal extent.
// ---------------------------------------------------------------------------
__global__ void __launch_bounds__(256, 2) k_pv(float* __restrict__ out)
{
    const int b = blockIdx.z;
    const int kmax = (blockIdx.y + 1) * 128;
    gemm_tile<false>(g_S + (size_t)b * TT * TT, TT,
                     g_V + (size_t)b * TT * DD, DD,
                     out + (size_t)b * TT * DD, DD,
                     kmax, 1.0f);
}

// ---------------------------------------------------------------------------
extern "C" void kernel_launch(void* const* d_in, const int* in_sizes, int n_in,
                              void* d_out, int out_size)
{
    const float* X  = (const float*)d_in[0];
    const float* Wq = (const float*)d_in[1];
    const float* Wk = (const float*)d_in[2];
    const float* Wv = (const float*)d_in[3];
    float* out = (float*)d_out;

    k_proj   <<<dim3(DD / 128, (BB * TT) / 128, 3), 256>>>(X, Wq, Wk, Wv);
    k_scores <<<dim3(TT / 128, TT / 128, BB), 256>>>();
    k_softmax<<<BB * TT, 256>>>();
    k_pv     <<<dim3(DD / 128, TT / 128, BB), 256>>>(out);
}